// round 16
// baseline (speedup 1.0000x reference)
#include <cuda_runtime.h>
#include <cuda_bf16.h>
#include <cstdint>
#include <cstddef>

#define NODES 64
#define DIM   256
#define TPB   256
#define PSTR  72    // padded row stride in bf16 elems (144 B, conflict-free ldsm)

// ---------------- helpers ----------------
__device__ __forceinline__ uint32_t smem_u32(const void* p) {
    uint32_t a;
    asm("{ .reg .u64 t; cvta.to.shared.u64 t, %1; cvt.u32.u64 %0, t; }" : "=r"(a) : "l"(p));
    return a;
}

__device__ __forceinline__ void ldsm_x4_trans(uint32_t& r0, uint32_t& r1,
                                              uint32_t& r2, uint32_t& r3, uint32_t addr) {
    asm volatile("ldmatrix.sync.aligned.m8n8.x4.trans.shared.b16 {%0,%1,%2,%3}, [%4];"
                 : "=r"(r0), "=r"(r1), "=r"(r2), "=r"(r3) : "r"(addr));
}

__device__ __forceinline__ void mma_bf16(float& c0, float& c1, float& c2, float& c3,
                                         uint32_t a0, uint32_t a1, uint32_t a2, uint32_t a3,
                                         uint32_t b0, uint32_t b1) {
    asm volatile(
        "mma.sync.aligned.m16n8k16.row.col.f32.bf16.bf16.f32 "
        "{%0,%1,%2,%3}, {%4,%5,%6,%7}, {%8,%9}, {%0,%1,%2,%3};"
        : "+f"(c0), "+f"(c1), "+f"(c2), "+f"(c3)
        : "r"(a0), "r"(a1), "r"(a2), "r"(a3), "r"(b0), "r"(b1));
}

__device__ __forceinline__ float fast_tanh(float v) {
    float e = __expf(2.0f * v);
    return 1.0f - __fdividef(2.0f, e + 1.0f);
}

__device__ __forceinline__ uint32_t pack_hi(float v0, float v1,
                                            float& r0, float& r1) {
    __nv_bfloat16 h0 = __float2bfloat16(v0);
    __nv_bfloat16 h1 = __float2bfloat16(v1);
    r0 = v0 - __bfloat162float(h0);
    r1 = v1 - __bfloat162float(h1);
    return (uint32_t)__bfloat16_as_ushort(h0)
         | ((uint32_t)__bfloat16_as_ushort(h1) << 16);
}
__device__ __forceinline__ uint32_t pack_lo(float r0, float r1) {
    return (uint32_t)__bfloat16_as_ushort(__float2bfloat16(r0))
         | ((uint32_t)__bfloat16_as_ushort(__float2bfloat16(r1)) << 16);
}

// merge-tree warp reduce of 8 per-lane partial sets -> per-lane row total.
// Row for lane l: R = 4*b2 + 2*b3 + b4
__device__ __forceinline__ float reduce8(float v[8], int lane) {
    float m[4];
    #pragma unroll
    for (int p = 0; p < 4; p++) {
        float s = (lane & 16) ? v[2 * p]     : v[2 * p + 1];
        float k = (lane & 16) ? v[2 * p + 1] : v[2 * p];
        m[p] = k + __shfl_xor_sync(0xffffffffu, s, 16);
    }
    float n[2];
    #pragma unroll
    for (int p = 0; p < 2; p++) {
        float s = (lane & 8) ? m[2 * p]     : m[2 * p + 1];
        float k = (lane & 8) ? m[2 * p + 1] : m[2 * p];
        n[p] = k + __shfl_xor_sync(0xffffffffu, s, 8);
    }
    float s = (lane & 4) ? n[0] : n[1];
    float k = (lane & 4) ? n[1] : n[0];
    float o = k + __shfl_xor_sync(0xffffffffu, s, 4);
    o += __shfl_xor_sync(0xffffffffu, o, 2);
    o += __shfl_xor_sync(0xffffffffu, o, 1);
    return o;
}

// ---------------- main kernel: 1 batch element per block, single launch ----------------
__global__ __launch_bounds__(TPB, 4)
void adj_attn_mma(const float* __restrict__ x,
                  const float* __restrict__ W1,
                  const float* __restrict__ W2,
                  const float* __restrict__ W3,
                  const float* __restrict__ bs,
                  const float* __restrict__ Vs,
                  float* __restrict__ out) {
    __shared__ __align__(16) __nv_bfloat16 tHiS[64 * PSTR];   // t[j][n] hi (j = k rows)
    __shared__ __align__(16) __nv_bfloat16 tLoS[64 * PSTR];   // t[j][n] lo
    __shared__ __align__(16) uint32_t sAfHi[2048];            // Vs mma fragments hi
    __shared__ __align__(16) uint32_t sAfLo[2048];            // Vs mma fragments lo
    __shared__ float lhsS[NODES];
    __shared__ float rhsS[NODES];
    __shared__ float redS[8];

    const int tid  = threadIdx.x;
    const int lane = tid & 31;
    const int w    = tid >> 5;

    // ---- stage A (=Vs) mma fragments into smem (L2-hot reads; hides in x-latency) ----
    // warp w handles mt = w&3, ks pair = 2*(w>>2)..+1; layout idx = (mt*4+ks)*128+lane*4+q
    {
        const int amt = w & 3;
        const int ks0 = (w >> 2) * 2;
        #pragma unroll
        for (int kk = 0; kk < 2; kk++) {
            const int ks = ks0 + kk;
            uint32_t hi[4], lo[4];
            #pragma unroll
            for (int q = 0; q < 4; q++) {
                int row = 16 * amt + (lane >> 2) + (q & 1) * 8;
                int col = 16 * ks + (lane & 3) * 2 + ((q >> 1) & 1) * 8;
                float2 v = *(const float2*)(Vs + row * 64 + col);
                float r0, r1;
                hi[q] = pack_hi(v.x, v.y, r0, r1);
                lo[q] = pack_lo(r0, r1);
            }
            const int u4 = (amt * 4 + ks) * 32 + lane;
            *(uint4*)(sAfHi + u4 * 4) = make_uint4(hi[0], hi[1], hi[2], hi[3]);
            *(uint4*)(sAfLo + u4 * 4) = make_uint4(lo[0], lo[1], lo[2], lo[3]);
        }
    }

    // ---- lhs/rhs dot products: warp w handles rows 8w..8w+7 ----
    const float w1   = *W1;
    const float4 w2a = *(const float4*)(W2 + 4 * lane);
    const float4 w2b = *(const float4*)(W2 + 128 + 4 * lane);
    const float4 w3a = *(const float4*)(W3 + 4 * lane);
    const float4 w3b = *(const float4*)(W3 + 128 + 4 * lane);
    const float* xb  = x + (size_t)blockIdx.x * (NODES * DIM);

    float a2[8], a3[8];
    #pragma unroll
    for (int r = 0; r < 8; r++) {
        const float* xr = xb + ((w << 3) + r) * DIM;
        float4 u = *(const float4*)(xr + (lane << 2));
        float4 v = *(const float4*)(xr + 128 + (lane << 2));
        a2[r] = u.x * w2a.x + u.y * w2a.y + u.z * w2a.z + u.w * w2a.w
              + v.x * w2b.x + v.y * w2b.y + v.z * w2b.z + v.w * w2b.w;
        a3[r] = u.x * w3a.x + u.y * w3a.y + u.z * w3a.z + u.w * w3a.w
              + v.x * w3b.x + v.y * w3b.y + v.z * w3b.z + v.w * w3b.w;
    }
    float s2 = reduce8(a2, lane);
    float s3 = reduce8(a3, lane);
    if ((lane & 3) == 0) {
        int R = 4 * ((lane >> 2) & 1) + 2 * ((lane >> 3) & 1) + ((lane >> 4) & 1);
        lhsS[(w << 3) + R] = w1 * s2;
        rhsS[(w << 3) + R] = s3;
    }
    __syncthreads();

    // ---- build t[j][n] = tanh(lhs[j]*rhs[n] + bs[j][n]) as bf16 hi/lo ----
    // Natural orientation: bias read DIRECT from gmem, coalesced. No transpose anywhere.
    {
        const int j  = tid >> 2;
        const int n0 = (tid & 3) * 16;
        const float lj = lhsS[j];
        #pragma unroll
        for (int c = 0; c < 2; c++) {
            const int n = n0 + c * 8;
            float4 r0 = *(const float4*)(rhsS + n);
            float4 r1 = *(const float4*)(rhsS + n + 4);
            float4 b0 = *(const float4*)(bs + j * 64 + n);
            float4 b1 = *(const float4*)(bs + j * 64 + n + 4);
            float tv[8];
            tv[0] = fast_tanh(fmaf(lj, r0.x, b0.x));
            tv[1] = fast_tanh(fmaf(lj, r0.y, b0.y));
            tv[2] = fast_tanh(fmaf(lj, r0.z, b0.z));
            tv[3] = fast_tanh(fmaf(lj, r0.w, b0.w));
            tv[4] = fast_tanh(fmaf(lj, r1.x, b1.x));
            tv[5] = fast_tanh(fmaf(lj, r1.y, b1.y));
            tv[6] = fast_tanh(fmaf(lj, r1.z, b1.z));
            tv[7] = fast_tanh(fmaf(lj, r1.w, b1.w));
            uint4 hw, lw;
            float q0, q1;
            hw.x = pack_hi(tv[0], tv[1], q0, q1); lw.x = pack_lo(q0, q1);
            hw.y = pack_hi(tv[2], tv[3], q0, q1); lw.y = pack_lo(q0, q1);
            hw.z = pack_hi(tv[4], tv[5], q0, q1); lw.z = pack_lo(q0, q1);
            hw.w = pack_hi(tv[6], tv[7], q0, q1); lw.w = pack_lo(q0, q1);
            *(uint4*)((char*)tHiS + (j * PSTR + n) * 2) = hw;
            *(uint4*)((char*)tLoS + (j * PSTR + n) * 2) = lw;
        }
    }
    __syncthreads();

    // ---- warp-level GEMM via ldsm.trans: warp w -> rows 16*(w>>1), cols 32*(w&1) ----
    const int mt = w >> 1;
    const int nh = w & 1;

    const uint32_t sTHi = smem_u32(tHiS);
    const uint32_t sTLo = smem_u32(tLoS);

    // trans addressing: lane -> row k = (lane&7) + ((lane>>3)&1)*8,
    //                   col n = nh*32 + ((lane>>4)&1)*8.
    // Tile order r0..r3 = (k0,n0),(k8,n0),(k0,n8),(k8,n8) — matches non-trans frags.
    const uint32_t bOff0 = (uint32_t)((((lane & 7) + ((lane >> 3) & 1) * 8) * PSTR
                                       + nh * 32 + ((lane >> 4) & 1) * 8) * 2);
    const uint32_t bOff1 = bOff0 + 32;                 // n + 16
    const uint32_t KSTEP = (uint32_t)(16 * PSTR * 2);  // k + 16 rows per ks

    float acc[16];
    #pragma unroll
    for (int i = 0; i < 16; i++) acc[i] = 0.0f;

    #pragma unroll
    for (int ks = 0; ks < 4; ks++) {
        const int fidx = (mt * 4 + ks) * 32 + lane;
        uint4 ah = *(const uint4*)(sAfHi + fidx * 4);
        uint4 al = *(const uint4*)(sAfLo + fidx * 4);
        const uint32_t joff = ks * KSTEP;
        uint32_t bh0, bh1, bh2, bh3, bh4, bh5, bh6, bh7;
        uint32_t bl0, bl1, bl2, bl3, bl4, bl5, bl6, bl7;
        ldsm_x4_trans(bh0, bh1, bh2, bh3, sTHi + bOff0 + joff);
        ldsm_x4_trans(bh4, bh5, bh6, bh7, sTHi + bOff1 + joff);
        ldsm_x4_trans(bl0, bl1, bl2, bl3, sTLo + bOff0 + joff);
        ldsm_x4_trans(bl4, bl5, bl6, bl7, sTLo + bOff1 + joff);
        // Ah*Bh
        mma_bf16(acc[0],  acc[1],  acc[2],  acc[3],  ah.x, ah.y, ah.z, ah.w, bh0, bh1);
        mma_bf16(acc[4],  acc[5],  acc[6],  acc[7],  ah.x, ah.y, ah.z, ah.w, bh2, bh3);
        mma_bf16(acc[8],  acc[9],  acc[10], acc[11], ah.x, ah.y, ah.z, ah.w, bh4, bh5);
        mma_bf16(acc[12], acc[13], acc[14], acc[15], ah.x, ah.y, ah.z, ah.w, bh6, bh7);
        // Ah*Bl
        mma_bf16(acc[0],  acc[1],  acc[2],  acc[3],  ah.x, ah.y, ah.z, ah.w, bl0, bl1);
        mma_bf16(acc[4],  acc[5],  acc[6],  acc[7],  ah.x, ah.y, ah.z, ah.w, bl2, bl3);
        mma_bf16(acc[8],  acc[9],  acc[10], acc[11], ah.x, ah.y, ah.z, ah.w, bl4, bl5);
        mma_bf16(acc[12], acc[13], acc[14], acc[15], ah.x, ah.y, ah.z, ah.w, bl6, bl7);
        // Al*Bh
        mma_bf16(acc[0],  acc[1],  acc[2],  acc[3],  al.x, al.y, al.z, al.w, bh0, bh1);
        mma_bf16(acc[4],  acc[5],  acc[6],  acc[7],  al.x, al.y, al.z, al.w, bh2, bh3);
        mma_bf16(acc[8],  acc[9],  acc[10], acc[11], al.x, al.y, al.z, al.w, bh4, bh5);
        mma_bf16(acc[12], acc[13], acc[14], acc[15], al.x, al.y, al.z, al.w, bh6, bh7);
    }

    // ---- softmax WITHOUT max subtraction (|s| <~ 76 -> exp finite in fp32) ----
    float lsum = 0.0f;
    #pragma unroll
    for (int i = 0; i < 16; i++) {
        acc[i] = __expf(acc[i]);
        lsum += acc[i];
    }
    #pragma unroll
    for (int sft = 16; sft > 0; sft >>= 1)
        lsum += __shfl_xor_sync(0xffffffffu, lsum, sft);
    if (lane == 0) redS[w] = lsum;
    __syncthreads();
    float tot = redS[0];
    #pragma unroll
    for (int i = 1; i < 8; i++) tot += redS[i];
    const float inv = 1.0f / tot;

    // ---- store: rows {16mt+lane/4, +8}, cols 32nh + g*8 + (lane%4)*2 ----
    float* ob = out + (size_t)blockIdx.x * (NODES * NODES);
    const int row0 = 16 * mt + (lane >> 2);
    const int col0 = 32 * nh + (lane & 3) * 2;
    #pragma unroll
    for (int g = 0; g < 4; g++) {
        float2 o;
        o.x = acc[g * 4 + 0] * inv;
        o.y = acc[g * 4 + 1] * inv;
        *(float2*)(ob + row0 * NODES + col0 + g * 8) = o;
        o.x = acc[g * 4 + 2] * inv;
        o.y = acc[g * 4 + 3] * inv;
        *(float2*)(ob + (row0 + 8) * NODES + col0 + g * 8) = o;
    }
}

extern "C" void kernel_launch(void* const* d_in, const int* in_sizes, int n_in,
                              void* d_out, int out_size) {
    const float* x  = (const float*)d_in[0];
    const float* W1 = (const float*)d_in[1];
    const float* W2 = (const float*)d_in[2];
    const float* W3 = (const float*)d_in[3];
    const float* bs = (const float*)d_in[4];
    const float* Vs = (const float*)d_in[5];
    float* out = (float*)d_out;

    const int B = in_sizes[0] / (NODES * DIM);   // 4096
    adj_attn_mma<<<B, TPB>>>(x, W1, W2, W3, bs, Vs, out);
}

// round 17
// speedup vs baseline: 1.1901x; 1.1901x over previous
#include <cuda_runtime.h>
#include <cuda_bf16.h>
#include <cstdint>
#include <cstddef>

#define NODES 64
#define DIM   256
#define TPB   256
#define PSTR  72    // padded row stride in bf16 elems (144 B, conflict-free ldsm)

// ---------------- device scratch (grid-constant precompute) ----------------
// A (=Vs) mma fragments, per-lane layout: idx = (mt*4+ks)*128 + lane*4 + q
__device__ __align__(16) uint32_t g_AfHi[2048];
__device__ __align__(16) uint32_t g_AfLo[2048];
__device__ __align__(16) float    g_bsT[4096];    // bsT[n][j] = bs[j][n]

// ---------------- helpers ----------------
__device__ __forceinline__ uint32_t smem_u32(const void* p) {
    uint32_t a;
    asm("{ .reg .u64 t; cvta.to.shared.u64 t, %1; cvt.u32.u64 %0, t; }" : "=r"(a) : "l"(p));
    return a;
}

__device__ __forceinline__ void ldsm_x4(uint32_t& r0, uint32_t& r1,
                                        uint32_t& r2, uint32_t& r3, uint32_t addr) {
    asm volatile("ldmatrix.sync.aligned.m8n8.x4.shared.b16 {%0,%1,%2,%3}, [%4];"
                 : "=r"(r0), "=r"(r1), "=r"(r2), "=r"(r3) : "r"(addr));
}

__device__ __forceinline__ void mma_bf16(float& c0, float& c1, float& c2, float& c3,
                                         uint32_t a0, uint32_t a1, uint32_t a2, uint32_t a3,
                                         uint32_t b0, uint32_t b1) {
    asm volatile(
        "mma.sync.aligned.m16n8k16.row.col.f32.bf16.bf16.f32 "
        "{%0,%1,%2,%3}, {%4,%5,%6,%7}, {%8,%9}, {%0,%1,%2,%3};"
        : "+f"(c0), "+f"(c1), "+f"(c2), "+f"(c3)
        : "r"(a0), "r"(a1), "r"(a2), "r"(a3), "r"(b0), "r"(b1));
}

// single-MUFU hardware tanh (sm_75+); max abs err ~1e-5, same order as bf16x3 residual
__device__ __forceinline__ float fast_tanh(float v) {
    float r;
    asm("tanh.approx.f32 %0, %1;" : "=f"(r) : "f"(v));
    return r;
}

__device__ __forceinline__ uint32_t pack_hi(float v0, float v1,
                                            float& r0, float& r1) {
    __nv_bfloat16 h0 = __float2bfloat16(v0);
    __nv_bfloat16 h1 = __float2bfloat16(v1);
    r0 = v0 - __bfloat162float(h0);
    r1 = v1 - __bfloat162float(h1);
    return (uint32_t)__bfloat16_as_ushort(h0)
         | ((uint32_t)__bfloat16_as_ushort(h1) << 16);
}
__device__ __forceinline__ uint32_t pack_lo(float r0, float r1) {
    return (uint32_t)__bfloat16_as_ushort(__float2bfloat16(r0))
         | ((uint32_t)__bfloat16_as_ushort(__float2bfloat16(r1)) << 16);
}

// merge-tree warp reduce of 8 per-lane partial sets -> per-lane row total.
// Row for lane l: R = 4*b2 + 2*b3 + b4
__device__ __forceinline__ float reduce8(float v[8], int lane) {
    float m[4];
    #pragma unroll
    for (int p = 0; p < 4; p++) {
        float s = (lane & 16) ? v[2 * p]     : v[2 * p + 1];
        float k = (lane & 16) ? v[2 * p + 1] : v[2 * p];
        m[p] = k + __shfl_xor_sync(0xffffffffu, s, 16);
    }
    float n[2];
    #pragma unroll
    for (int p = 0; p < 2; p++) {
        float s = (lane & 8) ? m[2 * p]     : m[2 * p + 1];
        float k = (lane & 8) ? m[2 * p + 1] : m[2 * p];
        n[p] = k + __shfl_xor_sync(0xffffffffu, s, 8);
    }
    float s = (lane & 4) ? n[0] : n[1];
    float k = (lane & 4) ? n[1] : n[0];
    float o = k + __shfl_xor_sync(0xffffffffu, s, 4);
    o += __shfl_xor_sync(0xffffffffu, o, 2);
    o += __shfl_xor_sync(0xffffffffu, o, 1);
    return o;
}

// ---------------- precompute: A mma fragments (hi/lo) + bsT ----------------
__global__ void precompute_kernel(const float* __restrict__ bs,
                                  const float* __restrict__ Vs) {
    int e = blockIdx.x * blockDim.x + threadIdx.x;   // 0..4095
    if (e < 2048) {
        int mt = e >> 9, ks = (e >> 7) & 3, lane = (e >> 2) & 31, q = e & 3;
        int row = 16 * mt + (lane >> 2) + (q & 1) * 8;
        int col = 16 * ks + (lane & 3) * 2 + ((q >> 1) & 1) * 8;
        float v0 = Vs[row * 64 + col];
        float v1 = Vs[row * 64 + col + 1];
        float r0, r1;
        uint32_t hw = pack_hi(v0, v1, r0, r1);
        g_AfHi[e] = hw;
        g_AfLo[e] = pack_lo(r0, r1);
    }
    {
        int i = e >> 6, j = e & 63;
        g_bsT[e] = bs[j * 64 + i];
    }
}

// ---------------- main kernel: 1 batch element per block ----------------
__global__ __launch_bounds__(TPB, 4)
void adj_attn_mma(const float* __restrict__ x,
                  const float* __restrict__ W1,
                  const float* __restrict__ W2,
                  const float* __restrict__ W3,
                  float* __restrict__ out) {
    __shared__ __align__(16) __nv_bfloat16 tHiS[64 * PSTR];   // tT[n][j] hi
    __shared__ __align__(16) __nv_bfloat16 tLoS[64 * PSTR];   // tT[n][j] lo
    __shared__ float lhsS[NODES];
    __shared__ float rhsS[NODES];
    __shared__ float redS[8];

    const int tid  = threadIdx.x;
    const int lane = tid & 31;
    const int w    = tid >> 5;

    // ---- lhs/rhs dot products: warp w handles rows 8w..8w+7 ----
    const float w1   = *W1;
    const float4 w2a = *(const float4*)(W2 + 4 * lane);
    const float4 w2b = *(const float4*)(W2 + 128 + 4 * lane);
    const float4 w3a = *(const float4*)(W3 + 4 * lane);
    const float4 w3b = *(const float4*)(W3 + 128 + 4 * lane);
    const float* xb  = x + (size_t)blockIdx.x * (NODES * DIM);

    float a2[8], a3[8];
    #pragma unroll
    for (int r = 0; r < 8; r++) {
        const float* xr = xb + ((w << 3) + r) * DIM;
        float4 u = *(const float4*)(xr + (lane << 2));
        float4 v = *(const float4*)(xr + 128 + (lane << 2));
        a2[r] = u.x * w2a.x + u.y * w2a.y + u.z * w2a.z + u.w * w2a.w
              + v.x * w2b.x + v.y * w2b.y + v.z * w2b.z + v.w * w2b.w;
        a3[r] = u.x * w3a.x + u.y * w3a.y + u.z * w3a.z + u.w * w3a.w
              + v.x * w3b.x + v.y * w3b.y + v.z * w3b.z + v.w * w3b.w;
    }
    float s2 = reduce8(a2, lane);
    float s3 = reduce8(a3, lane);
    if ((lane & 3) == 0) {
        int R = 4 * ((lane >> 2) & 1) + 2 * ((lane >> 3) & 1) + ((lane >> 4) & 1);
        lhsS[(w << 3) + R] = w1 * s2;
        rhsS[(w << 3) + R] = s3;
    }
    __syncthreads();

    // ---- build tT[n][j] = tanh(lhs[j]*rhs[n] + bsT[n][j]) as bf16 hi/lo ----
    {
        const int n  = tid >> 2;
        const int j0 = (tid & 3) * 16;
        const float rv = rhsS[n];
        #pragma unroll
        for (int c = 0; c < 2; c++) {
            const int j = j0 + c * 8;
            float4 l0 = *(const float4*)(lhsS + j);
            float4 l1 = *(const float4*)(lhsS + j + 4);
            float4 b0 = *(const float4*)(g_bsT + n * 64 + j);
            float4 b1 = *(const float4*)(g_bsT + n * 64 + j + 4);
            float tv[8];
            tv[0] = fast_tanh(fmaf(l0.x, rv, b0.x));
            tv[1] = fast_tanh(fmaf(l0.y, rv, b0.y));
            tv[2] = fast_tanh(fmaf(l0.z, rv, b0.z));
            tv[3] = fast_tanh(fmaf(l0.w, rv, b0.w));
            tv[4] = fast_tanh(fmaf(l1.x, rv, b1.x));
            tv[5] = fast_tanh(fmaf(l1.y, rv, b1.y));
            tv[6] = fast_tanh(fmaf(l1.z, rv, b1.z));
            tv[7] = fast_tanh(fmaf(l1.w, rv, b1.w));
            uint4 hw, lw;
            float r0, r1;
            hw.x = pack_hi(tv[0], tv[1], r0, r1); lw.x = pack_lo(r0, r1);
            hw.y = pack_hi(tv[2], tv[3], r0, r1); lw.y = pack_lo(r0, r1);
            hw.z = pack_hi(tv[4], tv[5], r0, r1); lw.z = pack_lo(r0, r1);
            hw.w = pack_hi(tv[6], tv[7], r0, r1); lw.w = pack_lo(r0, r1);
            *(uint4*)((char*)tHiS + (n * PSTR + j) * 2) = hw;
            *(uint4*)((char*)tLoS + (n * PSTR + j) * 2) = lw;
        }
    }
    __syncthreads();

    // ---- warp-level GEMM: warp w -> rows 16*(w>>1).., cols 32*(w&1).. ----
    const int mt = w >> 1;
    const int nh = w & 1;

    const uint32_t sTHi = smem_u32(tHiS);
    const uint32_t sTLo = smem_u32(tLoS);

    const uint32_t bOff0 = (uint32_t)(((nh * 32 + (lane & 7) + ((lane >> 4) & 1) * 8) * PSTR
                                       + ((lane >> 3) & 1) * 8) * 2);
    const uint32_t bOff1 = bOff0 + (uint32_t)(16 * PSTR * 2);

    float acc[16];
    #pragma unroll
    for (int i = 0; i < 16; i++) acc[i] = 0.0f;

    const uint4* fHi = (const uint4*)g_AfHi;   // [(mt*4+ks)*32 + lane]
    const uint4* fLo = (const uint4*)g_AfLo;

    #pragma unroll
    for (int ks = 0; ks < 4; ks++) {
        const int fidx = (mt * 4 + ks) * 32 + lane;
        uint4 ah = fHi[fidx];
        uint4 al = fLo[fidx];
        const uint32_t joff = (uint32_t)(ks * 32);
        uint32_t bh0, bh1, bh2, bh3, bh4, bh5, bh6, bh7;
        uint32_t bl0, bl1, bl2, bl3, bl4, bl5, bl6, bl7;
        ldsm_x4(bh0, bh1, bh2, bh3, sTHi + bOff0 + joff);
        ldsm_x4(bh4, bh5, bh6, bh7, sTHi + bOff1 + joff);
        ldsm_x4(bl0, bl1, bl2, bl3, sTLo + bOff0 + joff);
        ldsm_x4(bl4, bl5, bl6, bl7, sTLo + bOff1 + joff);
        // Ah*Bh
        mma_bf16(acc[0],  acc[1],  acc[2],  acc[3],  ah.x, ah.y, ah.z, ah.w, bh0, bh1);
        mma_bf16(acc[4],  acc[5],  acc[6],  acc[7],  ah.x, ah.y, ah.z, ah.w, bh2, bh3);
        mma_bf16(acc[8],  acc[9],  acc[10], acc[11], ah.x, ah.y, ah.z, ah.w, bh4, bh5);
        mma_bf16(acc[12], acc[13], acc[14], acc[15], ah.x, ah.y, ah.z, ah.w, bh6, bh7);
        // Ah*Bl
        mma_bf16(acc[0],  acc[1],  acc[2],  acc[3],  ah.x, ah.y, ah.z, ah.w, bl0, bl1);
        mma_bf16(acc[4],  acc[5],  acc[6],  acc[7],  ah.x, ah.y, ah.z, ah.w, bl2, bl3);
        mma_bf16(acc[8],  acc[9],  acc[10], acc[11], ah.x, ah.y, ah.z, ah.w, bl4, bl5);
        mma_bf16(acc[12], acc[13], acc[14], acc[15], ah.x, ah.y, ah.z, ah.w, bl6, bl7);
        // Al*Bh
        mma_bf16(acc[0],  acc[1],  acc[2],  acc[3],  al.x, al.y, al.z, al.w, bh0, bh1);
        mma_bf16(acc[4],  acc[5],  acc[6],  acc[7],  al.x, al.y, al.z, al.w, bh2, bh3);
        mma_bf16(acc[8],  acc[9],  acc[10], acc[11], al.x, al.y, al.z, al.w, bh4, bh5);
        mma_bf16(acc[12], acc[13], acc[14], acc[15], al.x, al.y, al.z, al.w, bh6, bh7);
    }

    // ---- softmax WITHOUT max subtraction (|s| <~ 76 -> exp finite in fp32) ----
    float lsum = 0.0f;
    #pragma unroll
    for (int i = 0; i < 16; i++) {
        acc[i] = __expf(acc[i]);
        lsum += acc[i];
    }
    #pragma unroll
    for (int sft = 16; sft > 0; sft >>= 1)
        lsum += __shfl_xor_sync(0xffffffffu, lsum, sft);
    if (lane == 0) redS[w] = lsum;
    __syncthreads();
    float tot = redS[0];
    #pragma unroll
    for (int i = 1; i < 8; i++) tot += redS[i];
    const float inv = 1.0f / tot;

    // ---- store: rows {16mt+lane/4, +8}, cols 32nh + g*8 + (lane%4)*2 ----
    float* ob = out + (size_t)blockIdx.x * (NODES * NODES);
    const int row0 = 16 * mt + (lane >> 2);
    const int col0 = 32 * nh + (lane & 3) * 2;
    #pragma unroll
    for (int g = 0; g < 4; g++) {
        float2 o;
        o.x = acc[g * 4 + 0] * inv;
        o.y = acc[g * 4 + 1] * inv;
        *(float2*)(ob + row0 * NODES + col0 + g * 8) = o;
        o.x = acc[g * 4 + 2] * inv;
        o.y = acc[g * 4 + 3] * inv;
        *(float2*)(ob + (row0 + 8) * NODES + col0 + g * 8) = o;
    }
}

extern "C" void kernel_launch(void* const* d_in, const int* in_sizes, int n_in,
                              void* d_out, int out_size) {
    const float* x  = (const float*)d_in[0];
    const float* W1 = (const float*)d_in[1];
    const float* W2 = (const float*)d_in[2];
    const float* W3 = (const float*)d_in[3];
    const float* bs = (const float*)d_in[4];
    const float* Vs = (const float*)d_in[5];
    float* out = (float*)d_out;

    const int B = in_sizes[0] / (NODES * DIM);   // 4096
    precompute_kernel<<<16, 256>>>(bs, Vs);
    adj_attn_mma<<<B, TPB>>>(x, W1, W2, W3, out);
}